// round 4
// baseline (speedup 1.0000x reference)
#include <cuda_runtime.h>
#include <cstdint>

#define B_   4
#define L1_  1024
#define D_   256
#define H_   8
#define HD_  32
#define L_   4
#define L2_  21760
#define NQ_  (B_ * L1_)          // 4096
#define MV_  (B_ * L2_)          // 87040

// ---------------- scratch (static device memory; no allocs) ----------------
__device__ float g_v[(size_t)MV_ * D_];        // value @ Wv^T  (89 MB)
__device__ float g_off[(size_t)NQ_ * 128];     // query @ Wbox^T + bbox
__device__ float g_aw[(size_t)NQ_ * 128];      // raw query @ Wattn^T + battn
__device__ float g_outpre[(size_t)NQ_ * D_];   // pre-projection out
__device__ float g_moutpre[(size_t)NQ_ * D_];  // pre-projection mout

// ---------------------------------------------------------------------------
// GEMM: C[M,N] = A[M,K] @ W[N,K]^T + bias[N];  optional per-row zero mask.
// BM=BN=64, BK=32, 256 threads, 4x4 per-thread microtile.
// ---------------------------------------------------------------------------
#define SA_ 68   // padded smem stride (floats)
__global__ void gemm_bias_kernel(const float* __restrict__ A,
                                 const float* __restrict__ W,
                                 const float* __restrict__ bias,
                                 float* __restrict__ C,
                                 int M, int N, int K,
                                 const unsigned char* __restrict__ mask)
{
    __shared__ float As[32 * SA_];
    __shared__ float Bs[32 * SA_];

    const int m0 = blockIdx.x * 64;
    const int n0 = blockIdx.y * 64;
    const int t  = threadIdx.x;
    const int tm = t >> 4;      // 0..15
    const int tn = t & 15;      // 0..15

    float acc[4][4];
#pragma unroll
    for (int i = 0; i < 4; i++)
#pragma unroll
        for (int j = 0; j < 4; j++) acc[i][j] = 0.f;

    for (int k0 = 0; k0 < K; k0 += 32) {
#pragma unroll
        for (int u = 0; u < 2; u++) {
            int f   = t + u * 256;
            int row = f >> 3;
            int kc  = (f & 7) << 2;
            float4 a4 = *(const float4*)(A + (size_t)(m0 + row) * K + k0 + kc);
            As[(kc + 0) * SA_ + row] = a4.x;
            As[(kc + 1) * SA_ + row] = a4.y;
            As[(kc + 2) * SA_ + row] = a4.z;
            As[(kc + 3) * SA_ + row] = a4.w;
            float4 b4 = *(const float4*)(W + (size_t)(n0 + row) * K + k0 + kc);
            Bs[(kc + 0) * SA_ + row] = b4.x;
            Bs[(kc + 1) * SA_ + row] = b4.y;
            Bs[(kc + 2) * SA_ + row] = b4.z;
            Bs[(kc + 3) * SA_ + row] = b4.w;
        }
        __syncthreads();

#pragma unroll
        for (int k = 0; k < 32; k++) {
            float4 av = *(const float4*)(As + k * SA_ + tm * 4);
            float4 bv = *(const float4*)(Bs + k * SA_ + tn * 4);
            float ar[4] = {av.x, av.y, av.z, av.w};
            float br[4] = {bv.x, bv.y, bv.z, bv.w};
#pragma unroll
            for (int i = 0; i < 4; i++)
#pragma unroll
                for (int j = 0; j < 4; j++) acc[i][j] += ar[i] * br[j];
        }
        __syncthreads();
    }

#pragma unroll
    for (int i = 0; i < 4; i++) {
        int r = m0 + tm * 4 + i;
        int c = n0 + tn * 4;
        bool zero = (mask != nullptr) && (mask[r] != 0);
        float4 o;
        o.x = zero ? 0.f : acc[i][0] + bias[c + 0];
        o.y = zero ? 0.f : acc[i][1] + bias[c + 1];
        o.z = zero ? 0.f : acc[i][2] + bias[c + 2];
        o.w = zero ? 0.f : acc[i][3] + bias[c + 3];
        *(float4*)(C + (size_t)r * N + c) = o;
    }
}

// ---------------------------------------------------------------------------
// Sampler: 1 block per query (4096 blocks, 256 threads).
// warp = head h, lane = channel hd. Computes sw/lw softmaxes, bilinear-samples
// g_v, accumulates into g_outpre / g_moutpre. Also writes the repeated aw
// tensor (b,l1,H,L,K,K) into awout (output #3).
// ---------------------------------------------------------------------------
__global__ void sample_kernel(const float* __restrict__ refwin,
                              float* __restrict__ awout)
{
    __shared__ float sh_sw[H_][64];
    __shared__ float sh_lw[H_][64];
    __shared__ float sh_raw[H_][16];

    const int bq   = blockIdx.x;
    const int b    = bq >> 10;
    const int h    = threadIdx.x >> 5;
    const int lane = threadIdx.x & 31;

    const float* raw = g_aw + (size_t)bq * 128 + h * 16;
    if (lane < 16) sh_raw[h][lane] = raw[lane];
    __syncwarp();

    // entries n = lane and lane+32 of the 64-entry repeated attention map
    float e[2];
    int   aidx[2];
#pragma unroll
    for (int tgt = 0; tgt < 2; tgt++) {
        int n = lane + 32 * tgt;
        int l = n >> 4, kk = n & 15, ii = kk >> 2, jj = kk & 3;
        int a = ((ii >> 1) << 1) + (jj >> 1);     // 0..3 within level
        aidx[tgt] = a;
        e[tgt] = sh_raw[h][l * 4 + a];
    }

    // output #3: repeated aw, layout (bq, h, l, i, j) -> bq*512 + h*64 + n
    awout[(size_t)bq * 512 + h * 64 + lane]      = e[0];
    awout[(size_t)bq * 512 + h * 64 + lane + 32] = e[1];

    // sw: softmax over all 64 repeated entries
    float m = fmaxf(e[0], e[1]);
#pragma unroll
    for (int o = 16; o > 0; o >>= 1) m = fmaxf(m, __shfl_xor_sync(0xffffffffu, m, o));
    float p0 = __expf(e[0] - m), p1 = __expf(e[1] - m);
    float s = p0 + p1;
#pragma unroll
    for (int o = 16; o > 0; o >>= 1) s += __shfl_xor_sync(0xffffffffu, s, o);
    float inv = 1.f / s;
    sh_sw[h][lane]      = p0 * inv;
    sh_sw[h][lane + 32] = p1 * inv;

    // lw: softmax over L (4 levels) for each (i,j) group
#pragma unroll
    for (int tgt = 0; tgt < 2; tgt++) {
        int a = aidx[tgt];
        float r0 = sh_raw[h][0 + a], r1 = sh_raw[h][4 + a];
        float r2 = sh_raw[h][8 + a], r3 = sh_raw[h][12 + a];
        float m4 = fmaxf(fmaxf(r0, r1), fmaxf(r2, r3));
        float s4 = __expf(r0 - m4) + __expf(r1 - m4) + __expf(r2 - m4) + __expf(r3 - m4);
        sh_lw[h][lane + 32 * tgt] = __expf(e[tgt] - m4) / s4;
    }
    __syncwarp();

    const float rcx = refwin[bq * 4 + 0];
    const float rcy = refwin[bq * 4 + 1];
    const float rsx = refwin[bq * 4 + 2];
    const float rsy = refwin[bq * 4 + 3];

    const int stA[4] = {0, 16384, 20480, 21504};
    const int whA[4] = {128, 64, 32, 16};

    const float* offp = g_off + (size_t)bq * 128 + h * 16;

    float acc_o = 0.f, acc_m = 0.f;

#pragma unroll
    for (int l = 0; l < L_; l++) {
        float o0 = offp[l * 4 + 0], o1 = offp[l * 4 + 1];
        float o2 = offp[l * 4 + 2], o3 = offp[l * 4 + 3];
        float cx = rcx + o0 * 0.125f * rsx;
        float cy = rcy + o1 * 0.125f * rsy;
        float sx = fmaxf(rsx + o2 * 0.125f * rsx, 0.f);
        float sy = fmaxf(rsy + o3 * 0.125f * rsy, 0.f);
        const int Wl = whA[l];
        const float fW = (float)Wl;
        const float* vb = g_v + ((size_t)(b * L2_ + stA[l])) * D_ + h * HD_ + lane;

#pragma unroll
        for (int i = 0; i < 4; i++) {
            float y   = (cy + ((float)i - 1.5f) * 0.25f * sy) * fW - 0.5f;
            float y0f = floorf(y);
            float fy  = y - y0f;
            int   y0  = (int)y0f;
            bool vy0 = (y0 >= 0) && (y0 < Wl);
            bool vy1 = (y0 >= -1) && (y0 < Wl - 1);
            int  cy0 = min(max(y0, 0), Wl - 1);
            int  cy1 = min(max(y0 + 1, 0), Wl - 1);

#pragma unroll
            for (int j = 0; j < 4; j++) {
                float x   = (cx + ((float)j - 1.5f) * 0.25f * sx) * fW - 0.5f;
                float x0f = floorf(x);
                float fx  = x - x0f;
                int   x0  = (int)x0f;
                bool vx0 = (x0 >= 0) && (x0 < Wl);
                bool vx1 = (x0 >= -1) && (x0 < Wl - 1);
                int  cx0 = min(max(x0, 0), Wl - 1);
                int  cx1 = min(max(x0 + 1, 0), Wl - 1);

                float w00 = (vx0 && vy0) ? (1.f - fx) * (1.f - fy) : 0.f;
                float w10 = (vx1 && vy0) ? fx * (1.f - fy) : 0.f;
                float w01 = (vx0 && vy1) ? (1.f - fx) * fy : 0.f;
                float w11 = (vx1 && vy1) ? fx * fy : 0.f;

                float val = w00 * vb[(size_t)(cy0 * Wl + cx0) * D_]
                          + w10 * vb[(size_t)(cy0 * Wl + cx1) * D_]
                          + w01 * vb[(size_t)(cy1 * Wl + cx0) * D_]
                          + w11 * vb[(size_t)(cy1 * Wl + cx1) * D_];

                int n = l * 16 + i * 4 + j;
                acc_o += sh_sw[h][n] * val;
                acc_m += sh_lw[h][n] * val;
            }
        }
    }

    const size_t od = (size_t)bq * D_ + h * HD_ + lane;
    g_outpre[od]  = acc_o;
    g_moutpre[od] = acc_m;
}

// ---------------------------------------------------------------------------
extern "C" void kernel_launch(void* const* d_in, const int* in_sizes, int n_in,
                              void* d_out, int out_size)
{
    const float* query = (const float*)d_in[0];   // (4,1024,256)
    const float* value = (const float*)d_in[1];   // (4,21760,256)
    const float* refw  = (const float*)d_in[2];   // (4,1024,4)
    const float* Wv    = (const float*)d_in[3];   // (256,256)
    const float* bv    = (const float*)d_in[4];   // (256,)
    const float* Wo    = (const float*)d_in[5];   // (256,256)
    const float* bo    = (const float*)d_in[6];   // (256,)
    const float* Wbox  = (const float*)d_in[7];   // (128,256)
    const float* bbox  = (const float*)d_in[8];   // (128,)
    const float* Wattn = (const float*)d_in[9];   // (128,256)
    const float* battn = (const float*)d_in[10];  // (128,)
    const unsigned char* vmask = (const unsigned char*)d_in[13]; // (4,21760) bool

    float* out   = (float*)d_out;                 // (4,1024,256)
    float* mout  = out  + (size_t)NQ_ * D_;       // (4,1024,256)
    float* awout = mout + (size_t)NQ_ * D_;       // (4,1024,8,4,4,4) = 4096*512

    float *pv, *poff, *paw, *pop, *pmp;
    cudaGetSymbolAddress((void**)&pv,   g_v);
    cudaGetSymbolAddress((void**)&poff, g_off);
    cudaGetSymbolAddress((void**)&paw,  g_aw);
    cudaGetSymbolAddress((void**)&pop,  g_outpre);
    cudaGetSymbolAddress((void**)&pmp,  g_moutpre);

    // 1) v = value @ Wv^T + bv, masked
    gemm_bias_kernel<<<dim3(MV_ / 64, D_ / 64), 256>>>(value, Wv, bv, pv,
                                                       MV_, D_, D_, vmask);
    // 2) off = query @ Wbox^T + bbox
    gemm_bias_kernel<<<dim3(NQ_ / 64, 128 / 64), 256>>>(query, Wbox, bbox, poff,
                                                        NQ_, 128, D_, nullptr);
    // 3) raw aw = query @ Wattn^T + battn (to scratch; sampler expands to out)
    gemm_bias_kernel<<<dim3(NQ_ / 64, 128 / 64), 256>>>(query, Wattn, battn, paw,
                                                        NQ_, 128, D_, nullptr);
    // 4) softmaxes + bilinear sampling + aw expansion
    sample_kernel<<<NQ_, 256>>>(refw, awout);

    // 5) out / mout = pre @ Wo^T + bo
    gemm_bias_kernel<<<dim3(NQ_ / 64, D_ / 64), 256>>>(pop, Wo, bo, out,
                                                       NQ_, D_, D_, nullptr);
    gemm_bias_kernel<<<dim3(NQ_ / 64, D_ / 64), 256>>>(pmp, Wo, bo, mout,
                                                       NQ_, D_, D_, nullptr);
}

// round 6
// speedup vs baseline: 1.6843x; 1.6843x over previous
#include <cuda_runtime.h>
#include <cuda_bf16.h>
#include <cstdint>

#define B_   4
#define L1_  1024
#define D_   256
#define H_   8
#define HD_  32
#define L_   4
#define L2_  21760
#define NQ_  (B_ * L1_)          // 4096
#define MV_  (B_ * L2_)          // 87040

// ---------------- scratch (static device memory; no allocs) ----------------
__device__ float g_v[(size_t)MV_ * D_];        // value @ Wv^T  (89 MB)
__device__ float g_off[(size_t)NQ_ * 128];     // query @ Wbox^T + bbox
__device__ float g_aw[(size_t)NQ_ * 128];      // raw query @ Wattn^T + battn
__device__ float g_outpre[(size_t)NQ_ * D_];   // pre-projection out
__device__ float g_moutpre[(size_t)NQ_ * D_];  // pre-projection mout

// ===========================================================================
// HMMA (mma.sync) helpers — valid on plain sm_103 target (no tcgen05).
// ===========================================================================
__device__ __forceinline__ uint32_t smem_u32(const void* p) {
    uint32_t a;
    asm("{ .reg .u64 t; cvta.to.shared.u64 t, %1; cvt.u32.u64 %0, t; }"
        : "=r"(a) : "l"(p));
    return a;
}
__device__ __forceinline__ void ldmx4(uint32_t addr, uint32_t& r0, uint32_t& r1,
                                      uint32_t& r2, uint32_t& r3) {
    asm volatile("ldmatrix.sync.aligned.m8n8.x4.shared.b16 {%0,%1,%2,%3}, [%4];"
                 : "=r"(r0), "=r"(r1), "=r"(r2), "=r"(r3) : "r"(addr));
}
__device__ __forceinline__ void mma16816(float* d, const uint32_t* a,
                                         const uint32_t* b) {
    asm volatile("mma.sync.aligned.m16n8k16.row.col.f32.bf16.bf16.f32 "
                 "{%0,%1,%2,%3}, {%4,%5,%6,%7}, {%8,%9}, {%0,%1,%2,%3};"
                 : "+f"(d[0]), "+f"(d[1]), "+f"(d[2]), "+f"(d[3])
                 : "r"(a[0]), "r"(a[1]), "r"(a[2]), "r"(a[3]),
                   "r"(b[0]), "r"(b[1]));
}

// ===========================================================================
// HMMA GEMM: C[M,256] = A[M,256] @ W[256,256]^T + bias, optional row mask.
// bf16 hi/lo split (3 passes: hh, hl, lh) with fp32 accumulation -> ~1e-6 err.
// CTA tile 128x128, 8 warps (4 in M x 2 in N), BK=32.
// ===========================================================================
#define RS_ 80   // smem row stride in bytes for 32 bf16 (64B data + 16B pad)

__global__ __launch_bounds__(256)
void hmma_gemm_kernel(const float* __restrict__ A,
                      const float* __restrict__ W,
                      const float* __restrict__ bias,
                      float* __restrict__ C,
                      const unsigned char* __restrict__ mask)
{
    __shared__ __align__(16) unsigned char smAh[128 * RS_];
    __shared__ __align__(16) unsigned char smAl[128 * RS_];
    __shared__ __align__(16) unsigned char smBh[128 * RS_];
    __shared__ __align__(16) unsigned char smBl[128 * RS_];
    __shared__ float bias_s[128];

    const int t    = threadIdx.x;
    const int wid  = t >> 5;
    const int lane = t & 31;
    const int wm   = wid & 3;       // warp row block (0..3) -> 32 rows
    const int wn   = wid >> 2;      // warp col block (0..1) -> 64 cols
    const int m0   = blockIdx.x * 128;
    const int n0   = blockIdx.y * 128;

    if (t < 128) bias_s[t] = bias[n0 + t];

    float acc[2][8][4];
#pragma unroll
    for (int mt = 0; mt < 2; mt++)
#pragma unroll
        for (int nt = 0; nt < 8; nt++)
#pragma unroll
            for (int i = 0; i < 4; i++) acc[mt][nt][i] = 0.f;

    const uint32_t uAh = smem_u32(smAh);
    const uint32_t uAl = smem_u32(smAl);
    const uint32_t uBh = smem_u32(smBh);
    const uint32_t uBl = smem_u32(smBl);

    for (int k0 = 0; k0 < 256; k0 += 32) {
        // ---- stage A(128x32) and W(128x32) fp32 -> bf16 hi/lo into smem ----
#pragma unroll
        for (int u = 0; u < 4; u++) {
            int f  = t + u * 256;       // 0..1023
            int r  = f >> 3;            // 0..127
            int c4 = f & 7;             // float4 column
            float4 v = *(const float4*)(A + (size_t)(m0 + r) * 256 + k0 + c4 * 4);
            __nv_bfloat162 h01 = __floats2bfloat162_rn(v.x, v.y);
            __nv_bfloat162 h23 = __floats2bfloat162_rn(v.z, v.w);
            float2 f01 = __bfloat1622float2(h01);
            float2 f23 = __bfloat1622float2(h23);
            __nv_bfloat162 l01 = __floats2bfloat162_rn(v.x - f01.x, v.y - f01.y);
            __nv_bfloat162 l23 = __floats2bfloat162_rn(v.z - f23.x, v.w - f23.y);
            *(__nv_bfloat162*)(smAh + r * RS_ + c4 * 8)     = h01;
            *(__nv_bfloat162*)(smAh + r * RS_ + c4 * 8 + 4) = h23;
            *(__nv_bfloat162*)(smAl + r * RS_ + c4 * 8)     = l01;
            *(__nv_bfloat162*)(smAl + r * RS_ + c4 * 8 + 4) = l23;

            float4 w = *(const float4*)(W + (size_t)(n0 + r) * 256 + k0 + c4 * 4);
            __nv_bfloat162 wh01 = __floats2bfloat162_rn(w.x, w.y);
            __nv_bfloat162 wh23 = __floats2bfloat162_rn(w.z, w.w);
            float2 wf01 = __bfloat1622float2(wh01);
            float2 wf23 = __bfloat1622float2(wh23);
            __nv_bfloat162 wl01 = __floats2bfloat162_rn(w.x - wf01.x, w.y - wf01.y);
            __nv_bfloat162 wl23 = __floats2bfloat162_rn(w.z - wf23.x, w.w - wf23.y);
            *(__nv_bfloat162*)(smBh + r * RS_ + c4 * 8)     = wh01;
            *(__nv_bfloat162*)(smBh + r * RS_ + c4 * 8 + 4) = wh23;
            *(__nv_bfloat162*)(smBl + r * RS_ + c4 * 8)     = wl01;
            *(__nv_bfloat162*)(smBl + r * RS_ + c4 * 8 + 4) = wl23;
        }
        __syncthreads();

#pragma unroll
        for (int s = 0; s < 2; s++) {          // two k16 steps per k-chunk
            const int kb = s * 32;             // byte offset of k16 within row

            // A fragments: lanes 0-15 -> rows 0-15 k-low, 16-31 -> k-high
            uint32_t ah[2][4], al[2][4];
#pragma unroll
            for (int mt = 0; mt < 2; mt++) {
                int row  = wm * 32 + mt * 16 + (lane & 15);
                int koff = kb + ((lane >> 4) << 4);
                ldmx4(uAh + row * RS_ + koff, ah[mt][0], ah[mt][1], ah[mt][2], ah[mt][3]);
                ldmx4(uAl + row * RS_ + koff, al[mt][0], al[mt][1], al[mt][2], al[mt][3]);
            }
            // B fragments: per x4 load, two n8 tiles x two k-halves
            uint32_t bh[8][2], bl[8][2];
#pragma unroll
            for (int p = 0; p < 4; p++) {
                int nrow = wn * 64 + p * 16 + (lane & 7) + (((lane >> 4) & 1) << 3);
                int koff = kb + (((lane >> 3) & 1) << 4);
                ldmx4(uBh + nrow * RS_ + koff,
                      bh[p*2][0], bh[p*2][1], bh[p*2+1][0], bh[p*2+1][1]);
                ldmx4(uBl + nrow * RS_ + koff,
                      bl[p*2][0], bl[p*2][1], bl[p*2+1][0], bl[p*2+1][1]);
            }
#pragma unroll
            for (int mt = 0; mt < 2; mt++)
#pragma unroll
                for (int nt = 0; nt < 8; nt++) {
                    mma16816(acc[mt][nt], ah[mt], bh[nt]);  // hi*hi
                    mma16816(acc[mt][nt], ah[mt], bl[nt]);  // hi*lo
                    mma16816(acc[mt][nt], al[mt], bh[nt]);  // lo*hi
                }
        }
        __syncthreads();
    }

    // ---- epilogue: bias + mask, direct float2 stores ----
    const int rw = lane >> 2;          // 0..7
    const int cw = (lane & 3) * 2;     // 0,2,4,6
#pragma unroll
    for (int mt = 0; mt < 2; mt++) {
        int r = m0 + wm * 32 + mt * 16 + rw;
        bool z0 = (mask != nullptr) && (mask[r] != 0);
        bool z1 = (mask != nullptr) && (mask[r + 8] != 0);
#pragma unroll
        for (int nt = 0; nt < 8; nt++) {
            int cl = wn * 64 + nt * 8 + cw;       // 0..127 within tile
            float b0 = bias_s[cl], b1 = bias_s[cl + 1];
            float2 v0, v1;
            v0.x = z0 ? 0.f : acc[mt][nt][0] + b0;
            v0.y = z0 ? 0.f : acc[mt][nt][1] + b1;
            v1.x = z1 ? 0.f : acc[mt][nt][2] + b0;
            v1.y = z1 ? 0.f : acc[mt][nt][3] + b1;
            *(float2*)(C + (size_t)r * 256 + n0 + cl)       = v0;
            *(float2*)(C + (size_t)(r + 8) * 256 + n0 + cl) = v1;
        }
    }
}

// ---------------------------------------------------------------------------
// SIMT GEMM for the small N=128 projections (off / aw).
// ---------------------------------------------------------------------------
#define SA_ 68
__global__ void gemm_bias_kernel(const float* __restrict__ A,
                                 const float* __restrict__ W,
                                 const float* __restrict__ bias,
                                 float* __restrict__ C,
                                 int M, int N, int K)
{
    __shared__ float As[32 * SA_];
    __shared__ float Bs[32 * SA_];

    const int m0 = blockIdx.x * 64;
    const int n0 = blockIdx.y * 64;
    const int t  = threadIdx.x;
    const int tm = t >> 4;
    const int tn = t & 15;

    float acc[4][4];
#pragma unroll
    for (int i = 0; i < 4; i++)
#pragma unroll
        for (int j = 0; j < 4; j++) acc[i][j] = 0.f;

    for (int k0 = 0; k0 < K; k0 += 32) {
#pragma unroll
        for (int u = 0; u < 2; u++) {
            int f   = t + u * 256;
            int row = f >> 3;
            int kc  = (f & 7) << 2;
            float4 a4 = *(const float4*)(A + (size_t)(m0 + row) * K + k0 + kc);
            As[(kc + 0) * SA_ + row] = a4.x;
            As[(kc + 1) * SA_ + row] = a4.y;
            As[(kc + 2) * SA_ + row] = a4.z;
            As[(kc + 3) * SA_ + row] = a4.w;
            float4 b4 = *(const float4*)(W + (size_t)(n0 + row) * K + k0 + kc);
            Bs[(kc + 0) * SA_ + row] = b4.x;
            Bs[(kc + 1) * SA_ + row] = b4.y;
            Bs[(kc + 2) * SA_ + row] = b4.z;
            Bs[(kc + 3) * SA_ + row] = b4.w;
        }
        __syncthreads();

#pragma unroll
        for (int k = 0; k < 32; k++) {
            float4 av = *(const float4*)(As + k * SA_ + tm * 4);
            float4 bv = *(const float4*)(Bs + k * SA_ + tn * 4);
            float ar[4] = {av.x, av.y, av.z, av.w};
            float br[4] = {bv.x, bv.y, bv.z, bv.w};
#pragma unroll
            for (int i = 0; i < 4; i++)
#pragma unroll
                for (int j = 0; j < 4; j++) acc[i][j] += ar[i] * br[j];
        }
        __syncthreads();
    }

#pragma unroll
    for (int i = 0; i < 4; i++) {
        int r = m0 + tm * 4 + i;
        int c = n0 + tn * 4;
        float4 o;
        o.x = acc[i][0] + bias[c + 0];
        o.y = acc[i][1] + bias[c + 1];
        o.z = acc[i][2] + bias[c + 2];
        o.w = acc[i][3] + bias[c + 3];
        *(float4*)(C + (size_t)r * N + c) = o;
    }
}

// ---------------------------------------------------------------------------
// Sampler: 1 block per query, warp = head, lane = channel.
// ---------------------------------------------------------------------------
__global__ void sample_kernel(const float* __restrict__ refwin,
                              float* __restrict__ awout)
{
    __shared__ float sh_sw[H_][64];
    __shared__ float sh_lw[H_][64];
    __shared__ float sh_raw[H_][16];

    const int bq   = blockIdx.x;
    const int b    = bq >> 10;
    const int h    = threadIdx.x >> 5;
    const int lane = threadIdx.x & 31;

    const float* raw = g_aw + (size_t)bq * 128 + h * 16;
    if (lane < 16) sh_raw[h][lane] = raw[lane];
    __syncwarp();

    float e[2];
    int   aidx[2];
#pragma unroll
    for (int tgt = 0; tgt < 2; tgt++) {
        int n = lane + 32 * tgt;
        int l = n >> 4, kk = n & 15, ii = kk >> 2, jj = kk & 3;
        int a = ((ii >> 1) << 1) + (jj >> 1);
        aidx[tgt] = a;
        e[tgt] = sh_raw[h][l * 4 + a];
    }

    awout[(size_t)bq * 512 + h * 64 + lane]      = e[0];
    awout[(size_t)bq * 512 + h * 64 + lane + 32] = e[1];

    float m = fmaxf(e[0], e[1]);
#pragma unroll
    for (int o = 16; o > 0; o >>= 1) m = fmaxf(m, __shfl_xor_sync(0xffffffffu, m, o));
    float p0 = __expf(e[0] - m), p1 = __expf(e[1] - m);
    float s = p0 + p1;
#pragma unroll
    for (int o = 16; o > 0; o >>= 1) s += __shfl_xor_sync(0xffffffffu, s, o);
    float inv = 1.f / s;
    sh_sw[h][lane]      = p0 * inv;
    sh_sw[h][lane + 32] = p1 * inv;

#pragma unroll
    for (int tgt = 0; tgt < 2; tgt++) {
        int a = aidx[tgt];
        float r0 = sh_raw[h][0 + a], r1 = sh_raw[h][4 + a];
        float r2 = sh_raw[h][8 + a], r3 = sh_raw[h][12 + a];
        float m4 = fmaxf(fmaxf(r0, r1), fmaxf(r2, r3));
        float s4 = __expf(r0 - m4) + __expf(r1 - m4) + __expf(r2 - m4) + __expf(r3 - m4);
        sh_lw[h][lane + 32 * tgt] = __expf(e[tgt] - m4) / s4;
    }
    __syncwarp();

    const float rcx = refwin[bq * 4 + 0];
    const float rcy = refwin[bq * 4 + 1];
    const float rsx = refwin[bq * 4 + 2];
    const float rsy = refwin[bq * 4 + 3];

    const int stA[4] = {0, 16384, 20480, 21504};
    const int whA[4] = {128, 64, 32, 16};

    const float* offp = g_off + (size_t)bq * 128 + h * 16;

    float acc_o = 0.f, acc_m = 0.f;

#pragma unroll
    for (int l = 0; l < L_; l++) {
        float o0 = offp[l * 4 + 0], o1 = offp[l * 4 + 1];
        float o2 = offp[l * 4 + 2], o3 = offp[l * 4 + 3];
        float cx = rcx + o0 * 0.125f * rsx;
        float cy = rcy + o1 * 0.125f * rsy;
        float sx = fmaxf(rsx + o2 * 0.125f * rsx, 0.f);
        float sy = fmaxf(rsy + o3 * 0.125f * rsy, 0.f);
        const int Wl = whA[l];
        const float fW = (float)Wl;
        const float* vb = g_v + ((size_t)(b * L2_ + stA[l])) * D_ + h * HD_ + lane;

#pragma unroll
        for (int i = 0; i < 4; i++) {
            float y   = (cy + ((float)i - 1.5f) * 0.25f * sy) * fW - 0.5f;
            float y0f = floorf(y);
            float fy  = y - y0f;
            int   y0  = (int)y0f;
            bool vy0 = (y0 >= 0) && (y0 < Wl);
            bool vy1 = (y0 >= -1) && (y0 < Wl - 1);
            int  cy0 = min(max(y0, 0), Wl - 1);
            int  cy1 = min(max(y0 + 1, 0), Wl - 1);

#pragma unroll
            for (int j = 0; j < 4; j++) {
                float x   = (cx + ((float)j - 1.5f) * 0.25f * sx) * fW - 0.5f;
                float x0f = floorf(x);
                float fx  = x - x0f;
                int   x0  = (int)x0f;
                bool vx0 = (x0 >= 0) && (x0 < Wl);
                bool vx1 = (x0 >= -1) && (x0 < Wl - 1);
                int  cx0 = min(max(x0, 0), Wl - 1);
                int  cx1 = min(max(x0 + 1, 0), Wl - 1);

                float w00 = (vx0 && vy0) ? (1.f - fx) * (1.f - fy) : 0.f;
                float w10 = (vx1 && vy0) ? fx * (1.f - fy) : 0.f;
                float w01 = (vx0 && vy1) ? (1.f - fx) * fy : 0.f;
                float w11 = (vx1 && vy1) ? fx * fy : 0.f;

                float val = w00 * vb[(size_t)(cy0 * Wl + cx0) * D_]
                          + w10 * vb[(size_t)(cy0 * Wl + cx1) * D_]
                          + w01 * vb[(size_t)(cy1 * Wl + cx0) * D_]
                          + w11 * vb[(size_t)(cy1 * Wl + cx1) * D_];

                int n = l * 16 + i * 4 + j;
                acc_o += sh_sw[h][n] * val;
                acc_m += sh_lw[h][n] * val;
            }
        }
    }

    const size_t od = (size_t)bq * D_ + h * HD_ + lane;
    g_outpre[od]  = acc_o;
    g_moutpre[od] = acc_m;
}

// ---------------------------------------------------------------------------
extern "C" void kernel_launch(void* const* d_in, const int* in_sizes, int n_in,
                              void* d_out, int out_size)
{
    const float* query = (const float*)d_in[0];
    const float* value = (const float*)d_in[1];
    const float* refw  = (const float*)d_in[2];
    const float* Wv    = (const float*)d_in[3];
    const float* bv    = (const float*)d_in[4];
    const float* Wo    = (const float*)d_in[5];
    const float* bo    = (const float*)d_in[6];
    const float* Wbox  = (const float*)d_in[7];
    const float* bbox  = (const float*)d_in[8];
    const float* Wattn = (const float*)d_in[9];
    const float* battn = (const float*)d_in[10];
    const unsigned char* vmask = (const unsigned char*)d_in[13];

    float* out   = (float*)d_out;
    float* mout  = out  + (size_t)NQ_ * D_;
    float* awout = mout + (size_t)NQ_ * D_;

    float *pv, *poff, *paw, *pop, *pmp;
    cudaGetSymbolAddress((void**)&pv,   g_v);
    cudaGetSymbolAddress((void**)&poff, g_off);
    cudaGetSymbolAddress((void**)&paw,  g_aw);
    cudaGetSymbolAddress((void**)&pop,  g_outpre);
    cudaGetSymbolAddress((void**)&pmp,  g_moutpre);

    // 1) v = value @ Wv^T + bv, masked   (HMMA tensor cores)
    hmma_gemm_kernel<<<dim3(MV_ / 128, 2), 256>>>(value, Wv, bv, pv, vmask);
    // 2) off = query @ Wbox^T + bbox     (SIMT, tiny)
    gemm_bias_kernel<<<dim3(NQ_ / 64, 2), 256>>>(query, Wbox, bbox, poff,
                                                 NQ_, 128, D_);
    // 3) raw aw = query @ Wattn^T + battn
    gemm_bias_kernel<<<dim3(NQ_ / 64, 2), 256>>>(query, Wattn, battn, paw,
                                                 NQ_, 128, D_);
    // 4) softmaxes + bilinear sampling + aw expansion
    sample_kernel<<<NQ_, 256>>>(refw, awout);
    // 5) out / mout projections          (HMMA tensor cores)
    hmma_gemm_kernel<<<dim3(NQ_ / 128, 2), 256>>>(pop, Wo, bo, out, nullptr);
    hmma_gemm_kernel<<<dim3(NQ_ / 128, 2), 256>>>(pmp, Wo, bo, mout, nullptr);
}